// round 1
// baseline (speedup 1.0000x reference)
#include <cuda_runtime.h>
#include <cuda_bf16.h>

#define IMG_W 512
#define IMG_H 512
#define ROWS_PER_BLOCK 32
#define NTHREADS 128   // 128 threads * 4 floats = 512 = full row

// 3x3 local variance, stride 1, zero pad 1, divisor 9 (matches unfold->mean semantics).
// One block = one (b,c) plane x 32-row band. Separable box sum:
//   per input row: horizontal 3-sum of v and v*v (register + smem halo),
//   vertical 3-sum via shift registers, then var = S2/9 - (S1/9)^2.
__global__ __launch_bounds__(NTHREADS)
void ChannelwiseVariance_85091892068508_kernel(const float* __restrict__ x,
                                               float* __restrict__ out)
{
    // Double-buffered staging row. Layout: [buf][4 + col], guard zeros at
    // index 3 (col -1) and index 4+IMG_W (col 512).
    __shared__ float srow[2][IMG_W + 8];

    const int tid = threadIdx.x;
    const int x4  = tid * 4;                      // first of 4 owned columns
    const int y0  = blockIdx.x * ROWS_PER_BLOCK;  // first output row of band
    const size_t plane = (size_t)blockIdx.y * (size_t)(IMG_H * IMG_W);

    if (tid == 0) {
        srow[0][3] = 0.0f; srow[0][4 + IMG_W] = 0.0f;
        srow[1][3] = 0.0f; srow[1][4 + IMG_W] = 0.0f;
    }
    // (guards are read only after the first __syncthreads below)

    // Rolling horizontal sums for the last 3 input rows (v and v^2), float4 each.
    float4 hv0, hv1, hv2;
    float4 hq0, hq1, hq2;

    const float inv9 = 1.0f / 9.0f;

    #pragma unroll 1
    for (int it = 0; it < ROWS_PER_BLOCK + 2; ++it) {
        const int r = y0 - 1 + it;               // input row (may be -1 or IMG_H)
        float4 v = make_float4(0.f, 0.f, 0.f, 0.f);
        if (r >= 0 && r < IMG_H) {
            v = *reinterpret_cast<const float4*>(x + plane + (size_t)r * IMG_W + x4);
        }

        const int buf = it & 1;
        *reinterpret_cast<float4*>(&srow[buf][4 + x4]) = v;
        __syncthreads();

        const float l  = srow[buf][4 + x4 - 1];  // col x4-1 (0 at left edge)
        const float rr = srow[buf][4 + x4 + 4];  // col x4+4 (0 at right edge)

        // Horizontal 3-sums for the 4 owned output columns.
        float4 hv, hq;
        hv.x = l   + v.x + v.y;
        hv.y = v.x + v.y + v.z;
        hv.z = v.y + v.z + v.w;
        hv.w = v.z + v.w + rr;

        const float lq = l * l, aq = v.x * v.x, bq = v.y * v.y,
                    cq = v.z * v.z, dq = v.w * v.w, rq = rr * rr;
        hq.x = lq + aq + bq;
        hq.y = aq + bq + cq;
        hq.z = bq + cq + dq;
        hq.w = cq + dq + rq;

        // Shift rolling window.
        hv0 = hv1; hv1 = hv2; hv2 = hv;
        hq0 = hq1; hq1 = hq2; hq2 = hq;

        if (it >= 2) {
            const int y = r - 1;                 // output row
            float4 S1, S2, o;
            S1.x = hv0.x + hv1.x + hv2.x;  S2.x = hq0.x + hq1.x + hq2.x;
            S1.y = hv0.y + hv1.y + hv2.y;  S2.y = hq0.y + hq1.y + hq2.y;
            S1.z = hv0.z + hv1.z + hv2.z;  S2.z = hq0.z + hq1.z + hq2.z;
            S1.w = hv0.w + hv1.w + hv2.w;  S2.w = hq0.w + hq1.w + hq2.w;

            const float m0 = S1.x * inv9, m1 = S1.y * inv9,
                        m2 = S1.z * inv9, m3 = S1.w * inv9;
            o.x = fmaf(-m0, m0, S2.x * inv9);
            o.y = fmaf(-m1, m1, S2.y * inv9);
            o.z = fmaf(-m2, m2, S2.z * inv9);
            o.w = fmaf(-m3, m3, S2.w * inv9);

            *reinterpret_cast<float4*>(out + plane + (size_t)y * IMG_W + x4) = o;
        }
    }
}

extern "C" void kernel_launch(void* const* d_in, const int* in_sizes, int n_in,
                              void* d_out, int out_size)
{
    const float* x = (const float*)d_in[0];
    float* out = (float*)d_out;

    const int planes = in_sizes[0] / (IMG_H * IMG_W);   // 8*32 = 256
    dim3 grid(IMG_H / ROWS_PER_BLOCK, planes);          // (16, 256)
    dim3 block(NTHREADS);
    ChannelwiseVariance_85091892068508_kernel<<<grid, block>>>(x, out);
}